// round 13
// baseline (speedup 1.0000x reference)
#include <cuda_runtime.h>

// Problem constants
#define Bc     32
#define Ic     1152
#define Oc     10
#define Dc     16
#define Hc     10
#define Sc     922
#define HALF_I 576
#define ROW    20          // padded row stride (floats), 16B-aligned
#define NPAIR  (Bc * Oc)   // 320
#define K1_THR 256
#define K2_THR 256

// Inter-kernel scratch
// g_part[pair][half][slot][17]: slot0 = T/N of half; slot 1+h = C_h/c_h of half
__device__ float g_part[NPAIR][2][11][17];

// K1 dynamic smem: u_s 576*20 f | vnS 576 f | red 8*17 f | det 1 | mark 5760 B
#define K1_SMEM ((HALF_I*ROW + HALF_I + 8*17 + 1) * 4 + Hc * HALF_I)

__device__ __forceinline__ float sqrt_approx(float x) {
    float r; asm("sqrt.approx.f32 %0, %1;" : "=f"(r) : "f"(x)); return r;
}

__device__ __forceinline__ void load_row_s(const float* __restrict__ rp, float f[16]) {
    float4 a = *(const float4*)(rp + 0);
    float4 b = *(const float4*)(rp + 4);
    float4 c = *(const float4*)(rp + 8);
    float4 d = *(const float4*)(rp + 12);
    f[0]=a.x; f[1]=a.y; f[2]=a.z;  f[3]=a.w;
    f[4]=b.x; f[5]=b.y; f[6]=b.z;  f[7]=b.w;
    f[8]=c.x; f[9]=c.y; f[10]=c.z; f[11]=c.w;
    f[12]=d.x; f[13]=d.y; f[14]=d.z; f[15]=d.w;
}

// ===== K1: mark-byte scan (NO atomics) + staged T/N + complement per half ==
extern "C" __global__ void __launch_bounds__(K1_THR, 4)
k1_partials(const float* __restrict__ u, const unsigned int* __restrict__ sidx_raw)
{
    extern __shared__ float sm[];
    float*         u_s  = sm;                      // [HALF_I][ROW]
    float*         vnS  = u_s + HALF_I * ROW;      // [HALF_I]
    float*         red  = vnS + HALF_I;            // [8][17]
    int*           det  = (int*)(red + 8 * 17);
    unsigned char* mark = (unsigned char*)(det + 1);  // [Hc][HALF_I] bytes

    const int o    = blockIdx.x;
    const int b    = blockIdx.y;
    const int half = blockIdx.z;
    const int pair = b * Oc + o;
    const int i0   = half * HALF_I;
    const int tid  = threadIdx.x;
    const int w    = tid >> 5;
    const int lane = tid & 31;

    // zero mark bytes (5760 B = 1440 words; strided -> extent-safe)
    {
        unsigned* mw = (unsigned*)mark;
        for (int t = tid; t < (Hc * HALF_I) / 4; t += K1_THR) mw[t] = 0u;
    }
    // dtype detect: int64 <=> odd 32-bit words of first 128 elems all zero
    if (w == 0) {
        unsigned a = 0;
        #pragma unroll
        for (int j = 0; j < 4; j++) a |= __ldg(sidx_raw + 2 * (lane * 4 + j) + 1);
        unsigned bal = __ballot_sync(0xffffffffu, a != 0);
        if (lane == 0) *det = (bal == 0) ? 1 : 0;
    }
    __syncthreads();
    const bool is64 = (*det != 0);

    // ---- stage this half's u rows (coalesced float4; 9*256 = 2304 exact) --
    {
        const float4* gp = (const float4*)u + ((size_t)((size_t)b * Ic + i0) * Oc + o) * 4;
        #pragma unroll
        for (int k = 0; k < 9; k++) {
            int t = tid + k * K1_THR;
            int i = t >> 2, q = t & 3;
            float4 v = __ldg(gp + (size_t)i * (Oc * 4) + q);
            *(float4*)&u_s[i * ROW + q * 4] = v;
        }
    }

    // ---- sidx scan: mark THIS half's sampled rows as bytes (no atomics) ----
    // indices are distinct per h -> no same-byte races; byte-enables handle
    // intra-word writes. EXTENT: 37*256 = 9472 >= Sc*Hc = 9220 with guard.
    {
        const size_t sbase = (((size_t)b * Sc) * Oc + o) * Hc;
        const uint2* p64 = (const uint2*)sidx_raw;
        #pragma unroll 4
        for (int k = 0; k < 37; k++) {
            int t = tid + k * K1_THR;
            if (t < Sc * Hc) {
                int s = (int)(((unsigned)t * 52429u) >> 19);   // t/10 for t<81920
                int h = t - s * 10;
                size_t off = sbase + (size_t)s * 100 + h;
                unsigned v = is64 ? __ldg(&p64[off]).x : __ldg(sidx_raw + off);
                unsigned loc = v - (unsigned)i0;
                if (loc < HALF_I) mark[h * HALF_I + loc] = 1;
            }
        }
    }
    __syncthreads();

    // ---- norms + T/N partials over this half (3*256 >= 576, guarded) ------
    {
        float tA[17];
        #pragma unroll
        for (int j = 0; j < 17; j++) tA[j] = 0.f;
        #pragma unroll
        for (int k = 0; k < 3; k++) {
            int i = tid + k * K1_THR;
            if (i < HALF_I) {
                float f[16];
                load_row_s(&u_s[i * ROW], f);
                float ss = 0.f;
                #pragma unroll
                for (int d = 0; d < Dc; d++) ss = fmaf(f[d], f[d], ss);
                float vn = sqrt_approx(ss);
                vnS[i] = vn;
                tA[16] += vn;
                #pragma unroll
                for (int d = 0; d < Dc; d++) tA[d] = fmaf(vn, f[d], tA[d]);
            }
        }
        #pragma unroll
        for (int off = 16; off; off >>= 1)
            #pragma unroll
            for (int j = 0; j < 17; j++)
                tA[j] += __shfl_down_sync(0xffffffffu, tA[j], off);
        if (lane == 0) {
            #pragma unroll
            for (int j = 0; j < 17; j++) red[w * 17 + j] = tA[j];
        }
    }
    __syncthreads();

    if (tid < 17) {
        float s = 0.f;
        #pragma unroll
        for (int ww = 0; ww < 8; ww++) s += red[ww * 17 + tid];
        g_part[pair][half][0][tid] = s;
    }

    // ---- complement gather from smem: warp w -> h = w; w<2 also h = w+8 ----
    #pragma unroll
    for (int rep = 0; rep < 2; rep++) {
        int hh = w + rep * 8;
        if (hh < Hc) {
            const unsigned char* mh = mark + hh * HALF_I;
            float cA[17];
            #pragma unroll
            for (int q = 0; q < 17; q++) cA[q] = 0.f;

            #pragma unroll 3
            for (int wd = 0; wd < 18; wd++) {
                int i = wd * 32 + lane;             // 18*32 = 576 exact
                if (mh[i] == 0) {                   // complement row
                    float f[16];
                    load_row_s(&u_s[i * ROW], f);
                    float vn = vnS[i];              // identical to T-pass value
                    cA[16] += vn;
                    #pragma unroll
                    for (int d = 0; d < Dc; d++) cA[d] = fmaf(vn, f[d], cA[d]);
                }
            }
            #pragma unroll
            for (int off = 16; off; off >>= 1)
                #pragma unroll
                for (int q = 0; q < 17; q++)
                    cA[q] += __shfl_down_sync(0xffffffffu, cA[q], off);
            if (lane == 0) {
                #pragma unroll
                for (int q = 0; q < 17; q++) g_part[pair][half][1 + hh][q] = cA[q];
            }
        }
    }
}

// ===== K2: monolithic per-pair losses, double-buffered chunks, emit ========
extern "C" __global__ void __launch_bounds__(K2_THR, 4)
k2_loss(const float* __restrict__ u, float* __restrict__ out)
{
    __shared__ float buf[2][128 * ROW];   // double-buffered 128-row chunks
    __shared__ float mu[Hc * Dc];
    __shared__ float red[8 * 5];
    __shared__ float loss_s[Hc];
    __shared__ int   hmin;

    const int o    = blockIdx.x;
    const int b    = blockIdx.y;
    const int pair = b * Oc + o;
    const int tid  = threadIdx.x;
    const int w    = tid >> 5;
    const int lane = tid & 31;
    const int r    = tid & 127;           // row slot within chunk
    const int g    = tid >> 7;            // 0 -> h 0..4, 1 -> h 5..9

    const float4* gp = (const float4*)u + ((size_t)b * Ic * Oc + o) * 4;
    const int i1 = (tid) >> 2,       q1 = tid & 3;          // stage slot A
    const int i2 = (tid + 256) >> 2, q2 = (tid + 256) & 3;  // stage slot B

    float4 preA, preB;
    // prefetch chunk 0
    preA = __ldg(gp + (size_t)(0 * 128 + i1) * (Oc * 4) + q1);
    preB = __ldg(gp + (size_t)(0 * 128 + i2) * (Oc * 4) + q2);

    // Mu[h][d] = (T - C_h) / (N - c_h)  (fixed-order, once per pair)
    if (tid < Hc * Dc) {
        int h = tid >> 4, d = tid & 15;
        float T = g_part[pair][0][0][d]      + g_part[pair][1][0][d];
        float N = g_part[pair][0][0][16]     + g_part[pair][1][0][16];
        float C = g_part[pair][0][1 + h][d]  + g_part[pair][1][1 + h][d];
        float c = g_part[pair][0][1 + h][16] + g_part[pair][1][1 + h][16];
        mu[tid] = (T - C) / (N - c);
    }
    // store chunk 0
    *(float4*)&buf[0][i1 * ROW + q1 * 4] = preA;
    *(float4*)&buf[0][i2 * ROW + q2 * 4] = preB;
    __syncthreads();

    // per-thread mu slice + ||mu||^2 for this thread's 5 hypotheses
    float mv[5][16], mmr[5];
    #pragma unroll
    for (int j = 0; j < 5; j++) {
        const float4* mp = (const float4*)&mu[(g * 5 + j) * 16];  // broadcast LDS
        float4 m0 = mp[0], m1 = mp[1], m2 = mp[2], m3 = mp[3];
        mv[j][0]=m0.x;  mv[j][1]=m0.y;  mv[j][2]=m0.z;  mv[j][3]=m0.w;
        mv[j][4]=m1.x;  mv[j][5]=m1.y;  mv[j][6]=m1.z;  mv[j][7]=m1.w;
        mv[j][8]=m2.x;  mv[j][9]=m2.y;  mv[j][10]=m2.z; mv[j][11]=m2.w;
        mv[j][12]=m3.x; mv[j][13]=m3.y; mv[j][14]=m3.z; mv[j][15]=m3.w;
        float s = 0.f;
        #pragma unroll
        for (int d = 0; d < Dc; d++) s = fmaf(mv[j][d], mv[j][d], s);
        mmr[j] = s;
    }

    // ---- pipelined chunk loop ---------------------------------------------
    float pl[5] = {0.f, 0.f, 0.f, 0.f, 0.f};
    for (int ch = 0; ch < 9; ch++) {
        if (ch < 8) {   // issue next chunk's loads (latency overlapped w/ compute)
            preA = __ldg(gp + (size_t)((ch + 1) * 128 + i1) * (Oc * 4) + q1);
            preB = __ldg(gp + (size_t)((ch + 1) * 128 + i2) * (Oc * 4) + q2);
        }
        // compute on current chunk
        {
            float f[16];
            load_row_s(&buf[ch & 1][r * ROW], f);
            float ss = 0.f;
            #pragma unroll
            for (int d = 0; d < Dc; d++) ss = fmaf(f[d], f[d], ss);
            #pragma unroll
            for (int j = 0; j < 5; j++) {
                float dot = 0.f;
                #pragma unroll
                for (int d = 0; d < Dc; d++) dot = fmaf(f[d], mv[j][d], dot);
                float val = fmaf(-2.f, dot, ss + mmr[j]);
                pl[j] += sqrt_approx(fmaxf(val, 0.f));
            }
        }
        if (ch < 8) {   // stage next chunk (regs -> smem; waits loads here)
            *(float4*)&buf[(ch + 1) & 1][i1 * ROW + q1 * 4] = preA;
            *(float4*)&buf[(ch + 1) & 1][i2 * ROW + q2 * 4] = preB;
        }
        __syncthreads();
    }

    // ---- reduce, argmin (first occurrence), emit --------------------------
    #pragma unroll
    for (int off = 16; off; off >>= 1)
        #pragma unroll
        for (int j = 0; j < 5; j++)
            pl[j] += __shfl_down_sync(0xffffffffu, pl[j], off);
    if (lane == 0) {
        #pragma unroll
        for (int j = 0; j < 5; j++) red[w * 5 + j] = pl[j];
    }
    __syncthreads();

    if (tid < Hc) {
        int g2 = tid / 5, j = tid - g2 * 5;
        float s = 0.f;
        #pragma unroll
        for (int ww = 0; ww < 4; ww++) s += red[(g2 * 4 + ww) * 5 + j];
        loss_s[tid] = s;
    }
    __syncthreads();
    if (tid == 0) {
        int hm = 0; float best = loss_s[0];
        #pragma unroll
        for (int h = 1; h < Hc; h++)
            if (loss_s[h] < best) { best = loss_s[h]; hm = h; }
        hmin = hm;
    }
    __syncthreads();
    if (tid < Dc)
        out[(size_t)pair * Dc + tid] = mu[hmin * Dc + tid];
}

extern "C" void kernel_launch(void* const* d_in, const int* in_sizes, int n_in,
                              void* d_out, int out_size)
{
    const float*        u    = (const float*)d_in[0];
    const unsigned int* sidx = (const unsigned int*)d_in[1];
    float*              out  = (float*)d_out;

    cudaFuncSetAttribute(k1_partials,
                         cudaFuncAttributeMaxDynamicSharedMemorySize, K1_SMEM);

    k1_partials<<<dim3(Oc, Bc, 2), K1_THR, K1_SMEM>>>(u, sidx);
    k2_loss<<<dim3(Oc, Bc), K2_THR>>>(u, out);
}